// round 1
// baseline (speedup 1.0000x reference)
#include <cuda_runtime.h>

#define S_LEN 2048
#define B_DIM 32
#define H_DIM 1024

// ---------------- scratch (no allocations allowed) ----------------
__device__ float g_scores[B_DIM * S_LEN];   // (B,S) pre-softmax scores
__device__ float g_t1[B_DIM * H_DIM];       // bias + hidden @ W1^T

// ---------------- packed f32x2 helpers (FFMA2 path) ----------------
__device__ __forceinline__ unsigned long long pack2(float lo, float hi) {
    unsigned long long r;
    asm("mov.b64 %0, {%1, %2};" : "=l"(r) : "f"(lo), "f"(hi));
    return r;
}
__device__ __forceinline__ void fma2(unsigned long long& d,
                                     unsigned long long a,
                                     unsigned long long b) {
    asm("fma.rn.f32x2 %0, %1, %2, %0;" : "+l"(d) : "l"(a), "l"(b));
}
__device__ __forceinline__ float2 unpack2(unsigned long long p) {
    float2 f;
    asm("mov.b64 {%0, %1}, %2;" : "=f"(f.x), "=f"(f.y) : "l"(p));
    return f;
}

// ---------------- K_init: zero scores + context region of d_out ----------------
__global__ void k_init(float* __restrict__ ctx) {
    int i = blockIdx.x * blockDim.x + threadIdx.x;   // 65536 threads
    if (i < B_DIM * S_LEN) g_scores[i] = 0.f;
    if (i < B_DIM * H_DIM) ctx[i] = 0.f;
}

// ---------------- K0: t1[b,h] = attn_b[h] + sum_k hidden[b,k] * W[h,k] ----------------
// one warp per output, float4 coalesced loads, shuffle reduce
__global__ void k0_t1(const float* __restrict__ hidden,
                      const float* __restrict__ attn_w,
                      const float* __restrict__ attn_b) {
    int w = (blockIdx.x * blockDim.x + threadIdx.x) >> 5;  // global warp id = output id
    int lane = threadIdx.x & 31;
    if (w >= B_DIM * H_DIM) return;
    int b = w >> 10;          // / H_DIM
    int h = w & (H_DIM - 1);
    const float4* hp = (const float4*)(hidden + (size_t)b * H_DIM);
    const float4* wp = (const float4*)(attn_w + (size_t)h * 2 * H_DIM);  // first H cols = W1
    float acc = 0.f;
#pragma unroll
    for (int i = 0; i < 8; i++) {
        int idx = i * 32 + lane;      // float4 index; covers k in [0,1024)
        float4 hv = hp[idx];
        float4 wv = wp[idx];
        acc += hv.x * wv.x + hv.y * wv.y + hv.z * wv.z + hv.w * wv.w;
    }
#pragma unroll
    for (int off = 16; off; off >>= 1) acc += __shfl_down_sync(0xffffffffu, acc, off);
    if (lane == 0) g_t1[w] = acc + attn_b[h];
}

// ---------------- K1: fused GEMM + tanh + dot(v) -> scores ----------------
// C[r,h] = sum_k enc[r,k] * W2[h,k], r = s*B+b  (M=65536, N=1024, K=1024)
// scores[b,s] += sum_h tanh(C[r,h] + t1[b,h]) * v[h]   (atomic over 16 N-tiles)
#define BM 128
#define BN 64
#define BK 16
#define LDA (BM + 4)
#define LDB (BN + 4)

__global__ __launch_bounds__(256) void k1_gemm_scores(
    const float* __restrict__ enc,
    const float* __restrict__ attn_w,
    const float* __restrict__ v)
{
    __shared__ __align__(16) float As[BK][LDA];   // transposed: As[k][m]
    __shared__ __align__(16) float Bs[BK][LDB];   // transposed: Bs[k][n]

    const int tid = threadIdx.x;
    const int tx = tid & 15;     // n group (4 cols)
    const int ty = tid >> 4;     // m group (8 rows)
    const int m0 = blockIdx.y * BM;
    const int n0 = blockIdx.x * BN;

    const int lrow = tid >> 2;          // 0..63
    const int lcol = (tid & 3) * 4;     // 0,4,8,12

    const float* w2 = attn_w + H_DIM;   // second half of each 2H-wide row

    unsigned long long acc[4][4];       // acc[i][j]: rows (ty*8+2i, ty*8+2i+1), col tx*4+j
#pragma unroll
    for (int i = 0; i < 4; i++)
#pragma unroll
        for (int j = 0; j < 4; j++) acc[i][j] = 0ull;

    for (int kk = 0; kk < H_DIM; kk += BK) {
        float4 a0 = *(const float4*)(enc + (size_t)(m0 + lrow) * H_DIM + kk + lcol);
        float4 a1 = *(const float4*)(enc + (size_t)(m0 + lrow + 64) * H_DIM + kk + lcol);
        float4 b0 = *(const float4*)(w2 + (size_t)(n0 + lrow) * (2 * H_DIM) + kk + lcol);
        __syncthreads();
        {
            float av0[4] = {a0.x, a0.y, a0.z, a0.w};
            float av1[4] = {a1.x, a1.y, a1.z, a1.w};
            float bv0[4] = {b0.x, b0.y, b0.z, b0.w};
#pragma unroll
            for (int j = 0; j < 4; j++) {
                As[lcol + j][lrow] = av0[j];
                As[lcol + j][lrow + 64] = av1[j];
                Bs[lcol + j][lrow] = bv0[j];
            }
        }
        __syncthreads();
#pragma unroll
        for (int k = 0; k < BK; k++) {
            ulonglong2 ap0 = *(const ulonglong2*)&As[k][ty * 8];      // rows pre-paired
            ulonglong2 ap1 = *(const ulonglong2*)&As[k][ty * 8 + 4];
            float4 bf = *(const float4*)&Bs[k][tx * 4];
            unsigned long long ap[4] = {ap0.x, ap0.y, ap1.x, ap1.y};
            unsigned long long bb[4] = {pack2(bf.x, bf.x), pack2(bf.y, bf.y),
                                        pack2(bf.z, bf.z), pack2(bf.w, bf.w)};
#pragma unroll
            for (int i = 0; i < 4; i++)
#pragma unroll
                for (int j = 0; j < 4; j++)
                    fma2(acc[i][j], ap[i], bb[j]);
        }
    }

    // ---------------- epilogue: tanh + dot(v) + segment-reduce + atomic ----------------
    float vj[4];
#pragma unroll
    for (int j = 0; j < 4; j++) vj[j] = v[n0 + tx * 4 + j];

#pragma unroll
    for (int ip = 0; ip < 4; ip++) {
        float2 c[4];
#pragma unroll
        for (int j = 0; j < 4; j++) c[j] = unpack2(acc[ip][j]);
#pragma unroll
        for (int half = 0; half < 2; half++) {
            int r = m0 + ty * 8 + ip * 2 + half;    // global row = s*B + b
            int b = r & (B_DIM - 1);
            int s = r >> 5;
            const float* t1p = g_t1 + (size_t)b * H_DIM + n0 + tx * 4;
            float rowsum = 0.f;
#pragma unroll
            for (int j = 0; j < 4; j++) {
                float cv = half ? c[j].y : c[j].x;
                rowsum += tanhf(cv + t1p[j]) * vj[j];
            }
            // reduce across the 16 lanes (tx) sharing this row
            rowsum += __shfl_down_sync(0xffffffffu, rowsum, 8, 16);
            rowsum += __shfl_down_sync(0xffffffffu, rowsum, 4, 16);
            rowsum += __shfl_down_sync(0xffffffffu, rowsum, 2, 16);
            rowsum += __shfl_down_sync(0xffffffffu, rowsum, 1, 16);
            if (tx == 0) atomicAdd(&g_scores[(size_t)b * S_LEN + s], rowsum);
        }
    }
}

// ---------------- K2: masked softmax over s, per batch ----------------
__global__ void k2_softmax(const int* __restrict__ lens, float* __restrict__ wout) {
    __shared__ float red[256];
    int b = blockIdx.x;
    int len = lens[b];
    const float* sc = g_scores + (size_t)b * S_LEN;
    int tid = threadIdx.x;

    float mx = -3.4e38f;
    for (int s = tid; s < len; s += 256) mx = fmaxf(mx, sc[s]);
    red[tid] = mx;
    __syncthreads();
    for (int off = 128; off; off >>= 1) {
        if (tid < off) red[tid] = fmaxf(red[tid], red[tid + off]);
        __syncthreads();
    }
    mx = red[0];
    __syncthreads();

    float sum = 0.f;
    for (int s = tid; s < len; s += 256) sum += expf(sc[s] - mx);
    red[tid] = sum;
    __syncthreads();
    for (int off = 128; off; off >>= 1) {
        if (tid < off) red[tid] += red[tid + off];
        __syncthreads();
    }
    float inv = 1.f / red[0];

    for (int s = tid; s < S_LEN; s += 256)
        wout[(size_t)b * S_LEN + s] = (s < len) ? expf(sc[s] - mx) * inv : 0.f;
}

// ---------------- K3: context[b,h] = sum_s w[b,s] * enc[s,b,h] ----------------
// skip s >= len (weights exactly 0 there). grid = (16 s-chunks, B)
__global__ void k3_context(const float* __restrict__ enc,
                           const float* __restrict__ wts,
                           const int* __restrict__ lens,
                           float* __restrict__ ctx)
{
    int b = blockIdx.y;
    int len = lens[b];
    int s0 = blockIdx.x * (S_LEN / 16);
    int s1 = min(s0 + (S_LEN / 16), len);
    if (s0 >= s1) return;
    int h = threadIdx.x * 4;    // 256 threads cover H=1024 via float4
    float4 acc = make_float4(0.f, 0.f, 0.f, 0.f);
    for (int s = s0; s < s1; s++) {
        float w = __ldg(&wts[(size_t)b * S_LEN + s]);
        float4 e = *(const float4*)(enc + ((size_t)(s * B_DIM + b)) * H_DIM + h);
        acc.x += w * e.x; acc.y += w * e.y; acc.z += w * e.z; acc.w += w * e.w;
    }
    float* c = ctx + (size_t)b * H_DIM + h;
    atomicAdd(c + 0, acc.x);
    atomicAdd(c + 1, acc.y);
    atomicAdd(c + 2, acc.z);
    atomicAdd(c + 3, acc.w);
}

// ---------------- launcher ----------------
extern "C" void kernel_launch(void* const* d_in, const int* in_sizes, int n_in,
                              void* d_out, int out_size) {
    const float* hidden = (const float*)d_in[0];   // (B,H)
    const float* enc    = (const float*)d_in[1];   // (S,B,H)
    const int*   lens   = (const int*)d_in[2];     // (B,)
    const float* attn_w = (const float*)d_in[3];   // (H,2H)
    const float* attn_b = (const float*)d_in[4];   // (H,)
    const float* v      = (const float*)d_in[5];   // (H,)

    float* out = (float*)d_out;
    float* ctx = out;                       // (B,H) first
    float* wts = out + B_DIM * H_DIM;       // (B,S) second

    k_init<<<256, 256>>>(ctx);
    k0_t1<<<(B_DIM * H_DIM) / 8, 256>>>(hidden, attn_w, attn_b);
    dim3 g1(H_DIM / BN, (S_LEN * B_DIM) / BM);
    k1_gemm_scores<<<g1, 256>>>(enc, attn_w, v);
    k2_softmax<<<B_DIM, 256>>>(lens, wts);
    dim3 g3(16, B_DIM);
    k3_context<<<g3, 256>>>(enc, wts, lens, ctx);
}

// round 3
// speedup vs baseline: 2.0696x; 2.0696x over previous
#include <cuda_runtime.h>
#include <cuda_bf16.h>

#define S_LEN 2048
#define B_DIM 32
#define H_DIM 1024
#define M_TOT (S_LEN * B_DIM)

// ---------------- scratch (static __device__, no allocs) ----------------
__device__ __nv_bfloat16 g_w2_hi[H_DIM * H_DIM];   // W2^T as [h][k], hi part
__device__ __nv_bfloat16 g_w2_lo[H_DIM * H_DIM];   // lo part
__device__ float g_t1[B_DIM * H_DIM];              // bias + hidden @ W1^T (fp32)
__device__ float g_scores[B_DIM * S_LEN];          // (B,S) pre-softmax

// ---------------- helpers ----------------
__device__ __forceinline__ unsigned smem_u32(const void* p) {
    unsigned a;
    asm("{ .reg .u64 t; cvta.to.shared.u64 t, %1; cvt.u32.u64 %0, t; }" : "=r"(a) : "l"(p));
    return a;
}
__device__ __forceinline__ uint4 ldsm_x4(unsigned addr) {
    uint4 r;
    asm volatile("ldmatrix.sync.aligned.m8n8.x4.shared.b16 {%0,%1,%2,%3}, [%4];"
                 : "=r"(r.x), "=r"(r.y), "=r"(r.z), "=r"(r.w) : "r"(addr));
    return r;
}
__device__ __forceinline__ void mma_bf16(float* c, uint4 a, unsigned b0, unsigned b1) {
    asm volatile(
        "mma.sync.aligned.m16n8k16.row.col.f32.bf16.bf16.f32 "
        "{%0,%1,%2,%3}, {%4,%5,%6,%7}, {%8,%9}, {%0,%1,%2,%3};"
        : "+f"(c[0]), "+f"(c[1]), "+f"(c[2]), "+f"(c[3])
        : "r"(a.x), "r"(a.y), "r"(a.z), "r"(a.w), "r"(b0), "r"(b1));
}
// pack two floats into bf16x2 (lo half = first arg)
__device__ __forceinline__ unsigned pack_bf16x2(float f0, float f1) {
    unsigned r;
    asm("cvt.rn.bf16x2.f32 %0, %1, %2;" : "=r"(r) : "f"(f1), "f"(f0));
    return r;
}

// ---------------- small kernels ----------------
__global__ void k_init(float* __restrict__ ctx) {
    int i = blockIdx.x * blockDim.x + threadIdx.x;
    if (i < B_DIM * S_LEN) g_scores[i] = 0.f;
    if (i < B_DIM * H_DIM) ctx[i] = 0.f;
}

__global__ void k_convert_w2(const float* __restrict__ attn_w) {
    int i = blockIdx.x * blockDim.x + threadIdx.x;     // 262144 float4s
    int row = i >> 8, c4 = i & 255;
    float4 x = *(const float4*)(attn_w + (size_t)row * (2 * H_DIM) + H_DIM + c4 * 4);
    float hx = __bfloat162float(__float2bfloat16(x.x));
    float hy = __bfloat162float(__float2bfloat16(x.y));
    float hz = __bfloat162float(__float2bfloat16(x.z));
    float hw = __bfloat162float(__float2bfloat16(x.w));
    uint2 hi = make_uint2(pack_bf16x2(x.x, x.y), pack_bf16x2(x.z, x.w));
    uint2 lo = make_uint2(pack_bf16x2(x.x - hx, x.y - hy), pack_bf16x2(x.z - hz, x.w - hw));
    ((uint2*)g_w2_hi)[i] = hi;
    ((uint2*)g_w2_lo)[i] = lo;
}

// t1[b,h] = attn_b[h] + hidden[b,:] . W1[h,:]
__global__ void k0_t1(const float* __restrict__ hidden,
                      const float* __restrict__ attn_w,
                      const float* __restrict__ attn_b) {
    int w = (blockIdx.x * blockDim.x + threadIdx.x) >> 5;
    int lane = threadIdx.x & 31;
    if (w >= B_DIM * H_DIM) return;
    int b = w >> 10;
    int h = w & (H_DIM - 1);
    const float4* hp = (const float4*)(hidden + (size_t)b * H_DIM);
    const float4* wp = (const float4*)(attn_w + (size_t)h * 2 * H_DIM);
    float acc = 0.f;
#pragma unroll
    for (int i = 0; i < 8; i++) {
        int idx = i * 32 + lane;
        float4 hv = hp[idx];
        float4 wv = wp[idx];
        acc += hv.x * wv.x + hv.y * wv.y + hv.z * wv.z + hv.w * wv.w;
    }
#pragma unroll
    for (int off = 16; off; off >>= 1) acc += __shfl_down_sync(0xffffffffu, acc, off);
    if (lane == 0) g_t1[w] = acc + attn_b[h];
}

// ---------------- K1: bf16 3-split GEMM (mma.sync) + tanh/v epilogue ----------------
#define BM 128
#define BN 128
#define BK 32
#define SSTR 40                      // smem stride in halves (pad 8): conflict-free ldmatrix
#define TILE_B (BM * SSTR * 2)       // 10240 bytes per sub-tile
#define STAGE_B (4 * TILE_B)         // A_hi, A_lo, B_hi, B_lo = 40960
#define A_HI 0
#define A_LO TILE_B
#define B_HI (2 * TILE_B)
#define B_LO (3 * TILE_B)
#define T1S_OFF  (2 * STAGE_B)       // 81920: 32*128 floats
#define VS_OFF   (T1S_OFF + 32 * 128 * 4)  // 98304: 128 floats
#define SROW_OFF (VS_OFF + 512)            // 98816: 128 floats
#define K1_SMEM  (SROW_OFF + 512)          // 99328

struct Regs { float4 a[4]; uint4 bh[2], bl[2]; };

__device__ __forceinline__ void ldg_tile(Regs& r, const float* enc, int m0, int n0,
                                         int kk, int tid) {
#pragma unroll
    for (int i = 0; i < 4; i++) {
        int idx = i * 256 + tid;           // 1024 float4s: A = 128x32 f32
        int row = idx >> 3, c4 = idx & 7;
        r.a[i] = *(const float4*)(enc + (size_t)(m0 + row) * H_DIM + kk + c4 * 4);
    }
#pragma unroll
    for (int i = 0; i < 2; i++) {
        int idx = i * 256 + tid;           // 512 uint4s: B = 128x32 bf16
        int row = idx >> 2, c8 = idx & 3;
        size_t off = (size_t)(n0 + row) * H_DIM + kk + c8 * 8;
        r.bh[i] = *(const uint4*)(g_w2_hi + off);
        r.bl[i] = *(const uint4*)(g_w2_lo + off);
    }
}

__device__ __forceinline__ void sts_tile(const Regs& r, char* sb, int tid) {
#pragma unroll
    for (int i = 0; i < 4; i++) {
        int idx = i * 256 + tid;
        int row = idx >> 3, c4 = idx & 7;
        float4 x = r.a[i];
        float hx = __bfloat162float(__float2bfloat16(x.x));
        float hy = __bfloat162float(__float2bfloat16(x.y));
        float hz = __bfloat162float(__float2bfloat16(x.z));
        float hw = __bfloat162float(__float2bfloat16(x.w));
        uint2 hi = make_uint2(pack_bf16x2(x.x, x.y), pack_bf16x2(x.z, x.w));
        uint2 lo = make_uint2(pack_bf16x2(x.x - hx, x.y - hy), pack_bf16x2(x.z - hz, x.w - hw));
        unsigned hoff = (unsigned)(row * SSTR + c4 * 4) * 2;   // bytes
        *(uint2*)(sb + A_HI + hoff) = hi;
        *(uint2*)(sb + A_LO + hoff) = lo;
    }
#pragma unroll
    for (int i = 0; i < 2; i++) {
        int idx = i * 256 + tid;
        int row = idx >> 2, c8 = idx & 3;
        unsigned hoff = (unsigned)(row * SSTR + c8 * 8) * 2;
        *(uint4*)(sb + B_HI + hoff) = r.bh[i];
        *(uint4*)(sb + B_LO + hoff) = r.bl[i];
    }
}

__global__ void __launch_bounds__(256, 1) k1_gemm(const float* __restrict__ enc,
                                                  const float* __restrict__ v) {
    extern __shared__ char smem[];
    const unsigned sbase = smem_u32(smem);
    const int tid = threadIdx.x;
    const int wid = tid >> 5;
    const int L = tid & 31;
    const int wm = wid & 3;            // 0..3 -> m offset
    const int wn = wid >> 2;           // 0..1 -> n offset
    const int m0 = blockIdx.y * BM;
    const int n0 = blockIdx.x * BN;

    // preload t1 tile (32 x 128), v slice (128), zero srow (128)
    float* t1s = (float*)(smem + T1S_OFF);
    float* vs  = (float*)(smem + VS_OFF);
    float* srow = (float*)(smem + SROW_OFF);
#pragma unroll
    for (int i = 0; i < 4; i++) {
        int idx = i * 256 + tid;           // 1024 float4s
        int b = idx >> 5, c4 = idx & 31;
        ((float4*)t1s)[idx] = *(const float4*)(g_t1 + (size_t)b * H_DIM + n0 + c4 * 4);
    }
    if (tid < 128) { vs[tid] = v[n0 + tid]; srow[tid] = 0.f; }

    float acc[2][8][4];
#pragma unroll
    for (int i = 0; i < 2; i++)
#pragma unroll
        for (int j = 0; j < 8; j++)
#pragma unroll
            for (int e = 0; e < 4; e++) acc[i][j][e] = 0.f;

    // ldmatrix lane address components
    const int a_m  = wm * 32 + ((L >> 3) & 1) * 8 + (L & 7);
    const int a_k8 = (L >> 4) * 8;
    const int b_n  = wn * 64 + (L >> 4) * 8 + (L & 7);
    const int b_k8 = ((L >> 3) & 1) * 8;

    Regs r;
    ldg_tile(r, enc, m0, n0, 0, tid);
    sts_tile(r, smem, tid);
    ldg_tile(r, enc, m0, n0, BK, tid);
    __syncthreads();

    const int NKT = H_DIM / BK;          // 32
    for (int kt = 0; kt < NKT; kt++) {
        if (kt + 1 < NKT) sts_tile(r, smem + ((kt + 1) & 1) * STAGE_B, tid);
        if (kt + 2 < NKT) ldg_tile(r, enc, m0, n0, (kt + 2) * BK, tid);

        const unsigned sb = sbase + (kt & 1) * STAGE_B;
#pragma unroll
        for (int ks = 0; ks < 2; ks++) {
            const int kb = ks * 16;
            uint4 ah0 = ldsm_x4(sb + A_HI + (unsigned)(a_m * SSTR + kb + a_k8) * 2);
            uint4 ah1 = ldsm_x4(sb + A_HI + (unsigned)((a_m + 16) * SSTR + kb + a_k8) * 2);
            uint4 al0 = ldsm_x4(sb + A_LO + (unsigned)(a_m * SSTR + kb + a_k8) * 2);
            uint4 al1 = ldsm_x4(sb + A_LO + (unsigned)((a_m + 16) * SSTR + kb + a_k8) * 2);
#pragma unroll
            for (int nf2 = 0; nf2 < 4; nf2++) {
                unsigned boff = (unsigned)((b_n + nf2 * 16) * SSTR + kb + b_k8) * 2;
                uint4 bh = ldsm_x4(sb + B_HI + boff);
                uint4 bl = ldsm_x4(sb + B_LO + boff);
                // nfrag = nf2*2 (bh.x,bh.y), nf2*2+1 (bh.z,bh.w)
                mma_bf16(acc[0][nf2 * 2],     ah0, bh.x, bh.y);
                mma_bf16(acc[0][nf2 * 2],     ah0, bl.x, bl.y);
                mma_bf16(acc[0][nf2 * 2],     al0, bh.x, bh.y);
                mma_bf16(acc[0][nf2 * 2 + 1], ah0, bh.z, bh.w);
                mma_bf16(acc[0][nf2 * 2 + 1], ah0, bl.z, bl.w);
                mma_bf16(acc[0][nf2 * 2 + 1], al0, bh.z, bh.w);
                mma_bf16(acc[1][nf2 * 2],     ah1, bh.x, bh.y);
                mma_bf16(acc[1][nf2 * 2],     ah1, bl.x, bl.y);
                mma_bf16(acc[1][nf2 * 2],     al1, bh.x, bh.y);
                mma_bf16(acc[1][nf2 * 2 + 1], ah1, bh.z, bh.w);
                mma_bf16(acc[1][nf2 * 2 + 1], ah1, bl.z, bl.w);
                mma_bf16(acc[1][nf2 * 2 + 1], al1, bh.z, bh.w);
            }
        }
        __syncthreads();
    }

    // ---------------- epilogue: tanh + v-dot + row reduce ----------------
#pragma unroll
    for (int mf = 0; mf < 2; mf++) {
        float rp0 = 0.f, rp1 = 0.f;
        const int b0 = mf * 16 + (L >> 2);        // (m0+...)&31, m0%32==0
        const int b1 = b0 + 8;
#pragma unroll
        for (int nf = 0; nf < 8; nf++) {
            const int c0 = wn * 64 + nf * 8 + (L & 3) * 2;
            const int c1 = c0 + 1;
            rp0 += tanhf(acc[mf][nf][0] + t1s[b0 * 128 + c0]) * vs[c0];
            rp0 += tanhf(acc[mf][nf][1] + t1s[b0 * 128 + c1]) * vs[c1];
            rp1 += tanhf(acc[mf][nf][2] + t1s[b1 * 128 + c0]) * vs[c0];
            rp1 += tanhf(acc[mf][nf][3] + t1s[b1 * 128 + c1]) * vs[c1];
        }
        rp0 += __shfl_xor_sync(0xffffffffu, rp0, 1);
        rp0 += __shfl_xor_sync(0xffffffffu, rp0, 2);
        rp1 += __shfl_xor_sync(0xffffffffu, rp1, 1);
        rp1 += __shfl_xor_sync(0xffffffffu, rp1, 2);
        if ((L & 3) == 0) {
            atomicAdd(&srow[wm * 32 + mf * 16 + (L >> 2)], rp0);
            atomicAdd(&srow[wm * 32 + mf * 16 + (L >> 2) + 8], rp1);
        }
    }
    __syncthreads();
    if (tid < 128) {
        int rowg = m0 + tid;
        atomicAdd(&g_scores[(tid & 31) * S_LEN + (rowg >> 5)], srow[tid]);
    }
}

// ---------------- softmax ----------------
__global__ void k2_softmax(const int* __restrict__ lens, float* __restrict__ wout) {
    __shared__ float red[256];
    int b = blockIdx.x;
    int len = lens[b];
    const float* sc = g_scores + (size_t)b * S_LEN;
    int tid = threadIdx.x;

    float mx = -3.4e38f;
    for (int s = tid; s < len; s += 256) mx = fmaxf(mx, sc[s]);
    red[tid] = mx;
    __syncthreads();
    for (int off = 128; off; off >>= 1) {
        if (tid < off) red[tid] = fmaxf(red[tid], red[tid + off]);
        __syncthreads();
    }
    mx = red[0];
    __syncthreads();

    float sum = 0.f;
    for (int s = tid; s < len; s += 256) sum += expf(sc[s] - mx);
    red[tid] = sum;
    __syncthreads();
    for (int off = 128; off; off >>= 1) {
        if (tid < off) red[tid] += red[tid + off];
        __syncthreads();
    }
    float inv = 1.f / red[0];

    for (int s = tid; s < S_LEN; s += 256)
        wout[(size_t)b * S_LEN + s] = (s < len) ? expf(sc[s] - mx) * inv : 0.f;
}

// ---------------- context ----------------
__global__ void k3_context(const float* __restrict__ enc,
                           const float* __restrict__ wts,
                           const int* __restrict__ lens,
                           float* __restrict__ ctx) {
    int b = blockIdx.y;
    int len = lens[b];
    int s0 = blockIdx.x * (S_LEN / 16);
    int s1 = min(s0 + (S_LEN / 16), len);
    if (s0 >= s1) return;
    int h = threadIdx.x * 4;
    float4 acc = make_float4(0.f, 0.f, 0.f, 0.f);
    for (int s = s0; s < s1; s++) {
        float w = __ldg(&wts[(size_t)b * S_LEN + s]);
        float4 e = *(const float4*)(enc + ((size_t)(s * B_DIM + b)) * H_DIM + h);
        acc.x += w * e.x; acc.y += w * e.y; acc.z += w * e.z; acc.w += w * e.w;
    }
    float* c = ctx + (size_t)b * H_DIM + h;
    atomicAdd(c + 0, acc.x);
    atomicAdd(c + 1, acc.y);
    atomicAdd(c + 2, acc.z);
    atomicAdd(c + 3, acc.w);
}

// ---------------- launcher ----------------
extern "C" void kernel_launch(void* const* d_in, const int* in_sizes, int n_in,
                              void* d_out, int out_size) {
    const float* hidden = (const float*)d_in[0];
    const float* enc    = (const float*)d_in[1];
    const int*   lens   = (const int*)d_in[2];
    const float* attn_w = (const float*)d_in[3];
    const float* attn_b = (const float*)d_in[4];
    const float* v      = (const float*)d_in[5];

    float* out = (float*)d_out;
    float* ctx = out;
    float* wts = out + B_DIM * H_DIM;

    cudaFuncSetAttribute(k1_gemm, cudaFuncAttributeMaxDynamicSharedMemorySize, K1_SMEM);

    k_init<<<256, 256>>>(ctx);
    k_convert_w2<<<1024, 256>>>(attn_w);
    k0_t1<<<4096, 256>>>(hidden, attn_w, attn_b);
    dim3 g1(H_DIM / BN, M_TOT / BM);
    k1_gemm<<<g1, 256, K1_SMEM>>>(enc, v);
    k2_softmax<<<B_DIM, 256>>>(lens, wts);
    dim3 g3(16, B_DIM);
    k3_context<<<g3, 256>>>(enc, wts, lens, ctx);
}

// round 4
// speedup vs baseline: 2.2442x; 1.0844x over previous
#include <cuda_runtime.h>
#include <cuda_bf16.h>

#define S_LEN 2048
#define B_DIM 32
#define H_DIM 1024
#define M_TOT (S_LEN * B_DIM)

// ---------------- scratch ----------------
__device__ __nv_bfloat16 g_w2_hi[H_DIM * H_DIM];
__device__ __nv_bfloat16 g_w2_lo[H_DIM * H_DIM];
__device__ float g_t1[B_DIM * H_DIM];
__device__ float g_scores[B_DIM * S_LEN];

// ---------------- helpers ----------------
__device__ __forceinline__ unsigned smem_u32(const void* p) {
    unsigned a;
    asm("{ .reg .u64 t; cvta.to.shared.u64 t, %1; cvt.u32.u64 %0, t; }" : "=r"(a) : "l"(p));
    return a;
}
__device__ __forceinline__ uint4 ldsm_x4(unsigned addr) {
    uint4 r;
    asm volatile("ldmatrix.sync.aligned.m8n8.x4.shared.b16 {%0,%1,%2,%3}, [%4];"
                 : "=r"(r.x), "=r"(r.y), "=r"(r.z), "=r"(r.w) : "r"(addr));
    return r;
}
__device__ __forceinline__ void mma_bf16(float* c, uint4 a, unsigned b0, unsigned b1) {
    asm volatile(
        "mma.sync.aligned.m16n8k16.row.col.f32.bf16.bf16.f32 "
        "{%0,%1,%2,%3}, {%4,%5,%6,%7}, {%8,%9}, {%0,%1,%2,%3};"
        : "+f"(c[0]), "+f"(c[1]), "+f"(c[2]), "+f"(c[3])
        : "r"(a.x), "r"(a.y), "r"(a.z), "r"(a.w), "r"(b0), "r"(b1));
}
__device__ __forceinline__ unsigned pack_bf16x2(float f0, float f1) {
    unsigned r;
    asm("cvt.rn.bf16x2.f32 %0, %1, %2;" : "=r"(r) : "f"(f1), "f"(f0));
    return r;
}
__device__ __forceinline__ void cp_async16(unsigned sdst, const void* gsrc) {
    unsigned long long g;
    asm("cvta.to.global.u64 %0, %1;" : "=l"(g) : "l"(gsrc));
    asm volatile("cp.async.cg.shared.global [%0], [%1], 16;" :: "r"(sdst), "l"(g) : "memory");
}
#define CP_COMMIT() asm volatile("cp.async.commit_group;" ::: "memory")
#define CP_WAIT0()  asm volatile("cp.async.wait_group 0;" ::: "memory")

// rational tanh (Eigen-style), 4 at a time with one Newton-refined RCP
__device__ __forceinline__ void tanh4(const float* x, float* y) {
    float al[4], be[4];
#pragma unroll
    for (int i = 0; i < 4; i++) {
        float xc = fminf(fmaxf(x[i], -7.90531110763549805f), 7.90531110763549805f);
        float t = xc * xc;
        float a = -2.76076847742355e-16f;
        a = fmaf(a, t, 2.00018790482477e-13f);
        a = fmaf(a, t, -8.60467152213735e-11f);
        a = fmaf(a, t, 5.12229709037114e-08f);
        a = fmaf(a, t, 1.48572235717979e-05f);
        a = fmaf(a, t, 6.37261928875436e-04f);
        a = fmaf(a, t, 4.89352455891786e-03f);
        al[i] = xc * a;
        float b = 1.19825839466702e-06f;
        b = fmaf(b, t, 1.18534705686654e-04f);
        b = fmaf(b, t, 2.26843463243900e-03f);
        be[i] = fmaf(b, t, 4.89352518554385e-03f);
    }
    float p01 = be[0] * be[1];
    float p23 = be[2] * be[3];
    float p = p01 * p23;
    float r;
    asm("rcp.approx.f32 %0, %1;" : "=f"(r) : "f"(p));
    r = r * fmaf(-p, r, 2.0f);            // Newton
    float q01 = r * p23, q23 = r * p01;
    y[0] = al[0] * (q01 * be[1]);
    y[1] = al[1] * (q01 * be[0]);
    y[2] = al[2] * (q23 * be[3]);
    y[3] = al[3] * (q23 * be[2]);
}

// ---------------- small kernels ----------------
__global__ void k_init(float* __restrict__ ctx) {
    int i = blockIdx.x * blockDim.x + threadIdx.x;
    if (i < B_DIM * S_LEN) g_scores[i] = 0.f;
    if (i < B_DIM * H_DIM) ctx[i] = 0.f;
}

__global__ void k_convert_w2(const float* __restrict__ attn_w) {
    int i = blockIdx.x * blockDim.x + threadIdx.x;     // 262144 float4s
    int row = i >> 8, c4 = i & 255;
    float4 x = *(const float4*)(attn_w + (size_t)row * (2 * H_DIM) + H_DIM + c4 * 4);
    float hx = __bfloat162float(__float2bfloat16(x.x));
    float hy = __bfloat162float(__float2bfloat16(x.y));
    float hz = __bfloat162float(__float2bfloat16(x.z));
    float hw = __bfloat162float(__float2bfloat16(x.w));
    uint2 hi = make_uint2(pack_bf16x2(x.x, x.y), pack_bf16x2(x.z, x.w));
    uint2 lo = make_uint2(pack_bf16x2(x.x - hx, x.y - hy), pack_bf16x2(x.z - hz, x.w - hw));
    ((uint2*)g_w2_hi)[i] = hi;
    ((uint2*)g_w2_lo)[i] = lo;
}

__global__ void k0_t1(const float* __restrict__ hidden,
                      const float* __restrict__ attn_w,
                      const float* __restrict__ attn_b) {
    int w = (blockIdx.x * blockDim.x + threadIdx.x) >> 5;
    int lane = threadIdx.x & 31;
    if (w >= B_DIM * H_DIM) return;
    int b = w >> 10;
    int h = w & (H_DIM - 1);
    const float4* hp = (const float4*)(hidden + (size_t)b * H_DIM);
    const float4* wp = (const float4*)(attn_w + (size_t)h * 2 * H_DIM);
    float acc = 0.f;
#pragma unroll
    for (int i = 0; i < 8; i++) {
        int idx = i * 32 + lane;
        float4 hv = hp[idx];
        float4 wv = wp[idx];
        acc += hv.x * wv.x + hv.y * wv.y + hv.z * wv.z + hv.w * wv.w;
    }
#pragma unroll
    for (int off = 16; off; off >>= 1) acc += __shfl_down_sync(0xffffffffu, acc, off);
    if (lane == 0) g_t1[w] = acc + attn_b[h];
}

// ---------------- K1: 128x256 CTA, 64x64 warp tiles, 3-split bf16 ----------------
#define BM 128
#define BN 256
#define BK 32
#define SSTR 40                       // halves; 80-byte rows (16B aligned, conflict-free)
#define A_HI 0
#define A_LO 10240
#define B_HI 20480
#define B_LO 40960
#define STAGE_B 61440
#define T1S_OFF (2 * STAGE_B)               // 122880: 32*256 f32 = 32768
#define VS_OFF  (T1S_OFF + 32768)           // 155648: 256 f32
#define SROW_OFF (VS_OFF + 1024)            // 156672: 128 f32
#define K1_SMEM  (SROW_OFF + 512)           // 157184

struct ARegs { float4 a[4]; };

__device__ __forceinline__ void ldg_a(ARegs& r, const float* enc, int m0, int kk, int tid) {
#pragma unroll
    for (int i = 0; i < 4; i++) {
        int idx = i * 256 + tid;
        int row = idx >> 3, c4 = idx & 7;
        r.a[i] = *(const float4*)(enc + (size_t)(m0 + row) * H_DIM + kk + c4 * 4);
    }
}
__device__ __forceinline__ void sts_a(const ARegs& r, char* sb, int tid) {
#pragma unroll
    for (int i = 0; i < 4; i++) {
        int idx = i * 256 + tid;
        int row = idx >> 3, c4 = idx & 7;
        float4 x = r.a[i];
        float hx = __bfloat162float(__float2bfloat16(x.x));
        float hy = __bfloat162float(__float2bfloat16(x.y));
        float hz = __bfloat162float(__float2bfloat16(x.z));
        float hw = __bfloat162float(__float2bfloat16(x.w));
        uint2 hi = make_uint2(pack_bf16x2(x.x, x.y), pack_bf16x2(x.z, x.w));
        uint2 lo = make_uint2(pack_bf16x2(x.x - hx, x.y - hy), pack_bf16x2(x.z - hz, x.w - hw));
        unsigned off = (unsigned)row * 80u + (unsigned)c4 * 8u;
        *(uint2*)(sb + A_HI + off) = hi;
        *(uint2*)(sb + A_LO + off) = lo;
    }
}
__device__ __forceinline__ void cpa_b(unsigned sb, int n0, int kk, int tid) {
#pragma unroll
    for (int i = 0; i < 4; i++) {
        int idx = i * 256 + tid;
        int row = idx >> 2, c16 = idx & 3;
        size_t goff = (size_t)(n0 + row) * H_DIM + kk + c16 * 8;
        unsigned soff = (unsigned)row * 80u + (unsigned)c16 * 16u;
        cp_async16(sb + B_HI + soff, g_w2_hi + goff);
        cp_async16(sb + B_LO + soff, g_w2_lo + goff);
    }
}

__global__ void __launch_bounds__(256, 1) k1_gemm(const float* __restrict__ enc,
                                                  const float* __restrict__ v) {
    extern __shared__ char smem[];
    const unsigned sbase = smem_u32(smem);
    const int tid = threadIdx.x;
    const int wid = tid >> 5;
    const int L = tid & 31;
    const int wm = wid & 1;             // 2 m-warps
    const int wn = wid >> 1;            // 4 n-warps
    const int m0 = blockIdx.y * BM;
    const int n0 = blockIdx.x * BN;

    float* t1s = (float*)(smem + T1S_OFF);
    float* vs  = (float*)(smem + VS_OFF);
    float* srow = (float*)(smem + SROW_OFF);
#pragma unroll
    for (int i = 0; i < 8; i++) {
        int idx = i * 256 + tid;            // 2048 float4s = 32x256 f32
        int b = idx >> 6, c4 = idx & 63;
        ((float4*)t1s)[idx] = *(const float4*)(g_t1 + (size_t)b * H_DIM + n0 + c4 * 4);
    }
    if (tid < 256) vs[tid] = v[n0 + tid];
    if (tid < 128) srow[tid] = 0.f;

    float acc[4][8][4];
#pragma unroll
    for (int i = 0; i < 4; i++)
#pragma unroll
        for (int j = 0; j < 8; j++)
#pragma unroll
            for (int e = 0; e < 4; e++) acc[i][j][e] = 0.f;

    const int a_mb = wm * 64 + ((L >> 3) & 1) * 8 + (L & 7);
    const int a_k8 = (L >> 4) * 8;
    const int b_nb = wn * 64 + (L >> 4) * 8 + (L & 7);
    const int b_k8 = ((L >> 3) & 1) * 8;

    ARegs r;
    ldg_a(r, enc, m0, 0, tid);
    sts_a(r, smem, tid);
    cpa_b(sbase, n0, 0, tid);
    CP_COMMIT();
    ldg_a(r, enc, m0, BK, tid);
    CP_WAIT0();
    __syncthreads();

    const int NKT = H_DIM / BK;              // 32
    for (int kt = 0; kt < NKT; kt++) {
        if (kt + 1 < NKT) {
            char* nxt = smem + ((kt + 1) & 1) * STAGE_B;
            sts_a(r, nxt, tid);
            cpa_b(sbase + ((kt + 1) & 1) * STAGE_B, n0, (kt + 1) * BK, tid);
            CP_COMMIT();
        }
        if (kt + 2 < NKT) ldg_a(r, enc, m0, (kt + 2) * BK, tid);

        const unsigned sb = sbase + (kt & 1) * STAGE_B;
#pragma unroll
        for (int ks = 0; ks < 2; ks++) {
            const unsigned koff = (unsigned)(ks * 16) * 2u;
            uint4 ah[4], al[4];
#pragma unroll
            for (int mf = 0; mf < 4; mf++) {
                unsigned aoff = (unsigned)(a_mb + mf * 16) * 80u + koff + (unsigned)a_k8 * 2u;
                ah[mf] = ldsm_x4(sb + A_HI + aoff);
                al[mf] = ldsm_x4(sb + A_LO + aoff);
            }
#pragma unroll
            for (int nf2 = 0; nf2 < 4; nf2++) {
                unsigned boff = (unsigned)(b_nb + nf2 * 16) * 80u + koff + (unsigned)b_k8 * 2u;
                uint4 bh = ldsm_x4(sb + B_HI + boff);
                uint4 bl = ldsm_x4(sb + B_LO + boff);
#pragma unroll
                for (int mf = 0; mf < 4; mf++) {
                    mma_bf16(acc[mf][nf2 * 2],     ah[mf], bh.x, bh.y);
                    mma_bf16(acc[mf][nf2 * 2],     ah[mf], bl.x, bl.y);
                    mma_bf16(acc[mf][nf2 * 2],     al[mf], bh.x, bh.y);
                    mma_bf16(acc[mf][nf2 * 2 + 1], ah[mf], bh.z, bh.w);
                    mma_bf16(acc[mf][nf2 * 2 + 1], ah[mf], bl.z, bl.w);
                    mma_bf16(acc[mf][nf2 * 2 + 1], al[mf], bh.z, bh.w);
                }
            }
        }
        if (kt + 1 < NKT) CP_WAIT0();
        __syncthreads();
    }

    // ---------------- epilogue ----------------
#pragma unroll
    for (int mf = 0; mf < 4; mf++) {
        float rp0 = 0.f, rp1 = 0.f;
        const int q = L >> 2;
        const int b0 = (mf * 16 + q) & 31;
        const int b1 = (mf * 16 + q + 8) & 31;
#pragma unroll
        for (int nf = 0; nf < 8; nf++) {
            const int c = wn * 64 + nf * 8 + (L & 3) * 2;
            float x[4], y[4];
            x[0] = acc[mf][nf][0] + t1s[b0 * 256 + c];
            x[1] = acc[mf][nf][1] + t1s[b0 * 256 + c + 1];
            x[2] = acc[mf][nf][2] + t1s[b1 * 256 + c];
            x[3] = acc[mf][nf][3] + t1s[b1 * 256 + c + 1];
            tanh4(x, y);
            rp0 += y[0] * vs[c] + y[1] * vs[c + 1];
            rp1 += y[2] * vs[c] + y[3] * vs[c + 1];
        }
        rp0 += __shfl_xor_sync(0xffffffffu, rp0, 1);
        rp0 += __shfl_xor_sync(0xffffffffu, rp0, 2);
        rp1 += __shfl_xor_sync(0xffffffffu, rp1, 1);
        rp1 += __shfl_xor_sync(0xffffffffu, rp1, 2);
        if ((L & 3) == 0) {
            atomicAdd(&srow[wm * 64 + mf * 16 + q], rp0);
            atomicAdd(&srow[wm * 64 + mf * 16 + q + 8], rp1);
        }
    }
    __syncthreads();
    if (tid < 128) {
        int rowg = m0 + tid;
        atomicAdd(&g_scores[(tid & 31) * S_LEN + (rowg >> 5)], srow[tid]);
    }
}

// ---------------- softmax ----------------
__global__ void k2_softmax(const int* __restrict__ lens, float* __restrict__ wout) {
    __shared__ float red[256];
    int b = blockIdx.x;
    int len = lens[b];
    const float* sc = g_scores + (size_t)b * S_LEN;
    int tid = threadIdx.x;

    float mx = -3.4e38f;
    for (int s = tid; s < len; s += 256) mx = fmaxf(mx, sc[s]);
    red[tid] = mx;
    __syncthreads();
    for (int off = 128; off; off >>= 1) {
        if (tid < off) red[tid] = fmaxf(red[tid], red[tid + off]);
        __syncthreads();
    }
    mx = red[0];
    __syncthreads();

    float sum = 0.f;
    for (int s = tid; s < len; s += 256) sum += expf(sc[s] - mx);
    red[tid] = sum;
    __syncthreads();
    for (int off = 128; off; off >>= 1) {
        if (tid < off) red[tid] += red[tid + off];
        __syncthreads();
    }
    float inv = 1.f / red[0];

    for (int s = tid; s < S_LEN; s += 256)
        wout[(size_t)b * S_LEN + s] = (s < len) ? expf(sc[s] - mx) * inv : 0.f;
}

// ---------------- context ----------------
__global__ void k3_context(const float* __restrict__ enc,
                           const float* __restrict__ wts,
                           const int* __restrict__ lens,
                           float* __restrict__ ctx) {
    int b = blockIdx.y;
    int len = lens[b];
    int s0 = blockIdx.x * (S_LEN / 16);
    int s1 = min(s0 + (S_LEN / 16), len);
    if (s0 >= s1) return;
    int h = threadIdx.x * 4;
    float4 acc = make_float4(0.f, 0.f, 0.f, 0.f);
    for (int s = s0; s < s1; s++) {
        float w = __ldg(&wts[(size_t)b * S_LEN + s]);
        float4 e = *(const float4*)(enc + ((size_t)(s * B_DIM + b)) * H_DIM + h);
        acc.x += w * e.x; acc.y += w * e.y; acc.z += w * e.z; acc.w += w * e.w;
    }
    float* c = ctx + (size_t)b * H_DIM + h;
    atomicAdd(c + 0, acc.x);
    atomicAdd(c + 1, acc.y);
    atomicAdd(c + 2, acc.z);
    atomicAdd(c + 3, acc.w);
}

// ---------------- launcher ----------------
extern "C" void kernel_launch(void* const* d_in, const int* in_sizes, int n_in,
                              void* d_out, int out_size) {
    const float* hidden = (const float*)d_in[0];
    const float* enc    = (const float*)d_in[1];
    const int*   lens   = (const int*)d_in[2];
    const float* attn_w = (const float*)d_in[3];
    const float* attn_b = (const float*)d_in[4];
    const float* v      = (const float*)d_in[5];

    float* out = (float*)d_out;
    float* ctx = out;
    float* wts = out + B_DIM * H_DIM;

    cudaFuncSetAttribute(k1_gemm, cudaFuncAttributeMaxDynamicSharedMemorySize, K1_SMEM);

    k_init<<<256, 256>>>(ctx);
    k_convert_w2<<<1024, 256>>>(attn_w);
    k0_t1<<<4096, 256>>>(hidden, attn_w, attn_b);
    dim3 g1(H_DIM / BN, M_TOT / BM);
    k1_gemm<<<g1, 256, K1_SMEM>>>(enc, v);
    k2_softmax<<<B_DIM, 256>>>(lens, wts);
    dim3 g3(16, B_DIM);
    k3_context<<<g3, 256>>>(enc, wts, lens, ctx);
}